// round 17
// baseline (speedup 1.0000x reference)
#include <cuda_runtime.h>
#include <cuda_fp16.h>
#include <cuda_bf16.h>
#include <math.h>
#include <stdint.h>

// ---------------- problem constants ----------------
#define Bz   64
#define Tt   12
#define Nn   1024
#define Hh   64
#define Mm   32
#define Kk   3
#define HOR  12
#define G4   256
#define Pp   195           // K*DIN = 3*65
#define KP   224           // P padded to multiple of 32
#define QT   72            // per-batch combT rows: 1 x + 64 h + 7 pad
#define NQ   (Bz*QT)       // 4608
#define BT   (Bz*Tt)       // 768
#define WMC  (Pp*G4)       // 49920

#define PADH  40           // smem halves per 32-k row (bank-perfect)
#define TILEA (128*PADH)   // 5120 halves per array per stage
#define STAGE (4*TILEA)    // Ah Al Bh Bl
#define SMEMB (2*STAGE*2)  // bytes: 2 stages * halves*2 = 81920
#define CPAD2 132

// ---------------- device scratch (fp16 hi/lo split) ----------------
__device__ __align__(16) __half g_Gh[(size_t)Kk*Nn*Nn];
__device__ __align__(16) __half g_Gl[(size_t)Kk*Nn*Nn];
__device__ __align__(16) __half g_cTh[(size_t)NQ*Nn];     // combT [q][m]
__device__ __align__(16) __half g_cTl[(size_t)NQ*Nn];
__device__ __align__(16) __half g_sch[(size_t)Bz*Nn*KP];  // sc [b][n][p]
__device__ __align__(16) __half g_scl[(size_t)Bz*Nn*KP];
__device__ __align__(16) __half g_WmTh[(size_t)BT*G4*KP]; // [bt][pg][p]
__device__ __align__(16) __half g_WmTl[(size_t)BT*G4*KP];
__device__ __align__(16) __half g_dWh[G4*KP];
__device__ __align__(16) __half g_dWl[G4*KP];
__device__ float g_c[(size_t)Bz*Hh*Nn];                   // cell [b][hq][n]
__device__ float g_Wm[(size_t)BT*WMC];
__device__ float g_bm[BT*G4];
__device__ float g_hid1[BT*64];
__device__ float g_hid2[BT*64];

// ---------------- helpers ----------------
__device__ __forceinline__ uint32_t smem_u32(const void* p) {
    uint32_t a;
    asm("{ .reg .u64 t; cvta.to.shared.u64 t, %1; cvt.u32.u64 %0, t; }" : "=r"(a) : "l"(p));
    return a;
}
__device__ __forceinline__ void cpa16(uint32_t dst, const void* src) {
    asm volatile("cp.async.cg.shared.global [%0], [%1], 16;" :: "r"(dst), "l"(src));
}
#define CP_COMMIT() asm volatile("cp.async.commit_group;" ::: "memory")
#define CP_WAIT1()  asm volatile("cp.async.wait_group 1;" ::: "memory")
#define CP_WAIT0()  asm volatile("cp.async.wait_group 0;" ::: "memory")

__device__ __forceinline__ void mma16(float c[4], const uint32_t a[4], const uint32_t b[2]) {
    asm volatile("mma.sync.aligned.m16n8k16.row.col.f32.f16.f16.f32 "
        "{%0,%1,%2,%3}, {%4,%5,%6,%7}, {%8,%9}, {%0,%1,%2,%3};"
        : "+f"(c[0]), "+f"(c[1]), "+f"(c[2]), "+f"(c[3])
        : "r"(a[0]), "r"(a[1]), "r"(a[2]), "r"(a[3]), "r"(b[0]), "r"(b[1]));
}

__device__ __forceinline__ void ldsm4(uint32_t r[4], uint32_t a) {
    asm volatile("ldmatrix.sync.aligned.m8n8.x4.shared.b16 {%0,%1,%2,%3}, [%4];"
        : "=r"(r[0]), "=r"(r[1]), "=r"(r[2]), "=r"(r[3]) : "r"(a));
}

__device__ __forceinline__ void splitw(float x, __half& hi, __half& lo) {
    hi = __float2half(x);
    lo = __float2half(x - __half2float(hi));
}

// fragment+mma block via ldmatrix: one 32-k chunk, warp tile 64x32, fp16x3
__device__ __forceinline__ void frag_mma_block(
    uint32_t sAh, uint32_t sAl, uint32_t sBh, uint32_t sBl,
    int lane, int wm, int wn, float c[4][4][4])
{
    const int lrow = lane & 15;
    const int lcol = (lane >> 4) * 8;
    #pragma unroll
    for (int ks = 0; ks < 2; ks++) {
        const int kb0 = ks * 16 + lcol;
        uint32_t ah[4][4], al[4][4];
        #pragma unroll
        for (int mt = 0; mt < 4; mt++) {
            uint32_t off = (uint32_t)((wm * 64 + mt * 16 + lrow) * PADH + kb0) * 2;
            ldsm4(ah[mt], sAh + off);
            ldsm4(al[mt], sAl + off);
        }
        #pragma unroll
        for (int np = 0; np < 2; np++) {          // nt pairs (0,1) and (2,3)
            uint32_t boff = (uint32_t)((wn * 32 + np * 16 + lrow) * PADH + kb0) * 2;
            uint32_t bh[4], bl[4];
            ldsm4(bh, sBh + boff);
            ldsm4(bl, sBl + boff);
            #pragma unroll
            for (int sub = 0; sub < 2; sub++) {
                int nt = np * 2 + sub;
                uint32_t bhv[2] = {bh[sub], bh[sub + 2]};
                uint32_t blv[2] = {bl[sub], bl[sub + 2]};
                #pragma unroll
                for (int mt = 0; mt < 4; mt++) {
                    mma16(c[mt][nt], ah[mt], bhv);
                    mma16(c[mt][nt], al[mt], bhv);
                    mma16(c[mt][nt], ah[mt], blv);
                }
            }
        }
    }
}

// ---------------- init / conversion ----------------
__global__ void zero_kernel() {
    size_t i = (size_t)blockIdx.x * 256 + threadIdx.x;
    __half z = __float2half(0.f);
    g_sch[i] = z; g_scl[i] = z;
    if (i < (size_t)NQ * Nn)      { g_cTh[i] = z; g_cTl[i] = z; }
    if (i < (size_t)Bz * Hh * Nn) g_c[i] = 0.f;
}
__global__ void splitG_kernel(const float* __restrict__ G) {
    size_t i = (size_t)blockIdx.x * 256 + threadIdx.x;
    __half hi, lo; splitw(G[i], hi, lo);
    g_Gh[i] = hi; g_Gl[i] = lo;
}
__global__ void xrow_kernel(const float* __restrict__ xs, int t) {
    int g = blockIdx.x * 256 + threadIdx.x;
    int b = g >> 10, n = g & 1023;
    __half hi, lo; splitw(xs[((size_t)(b * Tt + t)) * Nn + n], hi, lo);
    size_t o = ((size_t)(b * QT)) * Nn + n;
    g_cTh[o] = hi; g_cTl[o] = lo;
}
__global__ void zerox_kernel() {
    int g = blockIdx.x * 256 + threadIdx.x;
    int b = g >> 10, n = g & 1023;
    size_t o = ((size_t)(b * QT)) * Nn + n;
    __half z = __float2half(0.f);
    g_cTh[o] = z; g_cTl[o] = z;
}

// ---------------- meta MLPs ----------------
__global__ void meta1_kernel(const float* __restrict__ xm,
                             const float* __restrict__ lw1w, const float* __restrict__ lw1b,
                             const float* __restrict__ lb1w, const float* __restrict__ lb1b) {
    int bt = blockIdx.x;
    int o = threadIdx.x & 63;
    bool second = threadIdx.x >= 64;
    const float* W = second ? lb1w : lw1w;
    const float* bi = second ? lb1b : lw1b;
    float acc = bi[o];
    const float* x = xm + bt * Mm;
    #pragma unroll
    for (int m = 0; m < Mm; m++) acc += x[m] * W[m * 64 + o];
    acc = fmaxf(acc, 0.f);
    if (second) g_hid2[bt * 64 + o] = acc;
    else        g_hid1[bt * 64 + o] = acc;
}

__global__ void meta2_kernel(const float* __restrict__ lw2w, const float* __restrict__ lw2b) {
    int q0 = blockIdx.x * 256;
    int r0 = blockIdx.y * 16;
    __shared__ float hs[16][65];
    int tid = threadIdx.x;
    {
        int r = tid >> 6, c = tid & 63;
        #pragma unroll
        for (int i = 0; i < 4; i++)
            hs[r + i * 4][c] = g_hid1[(r0 + r + i * 4) * 64 + c];
    }
    __syncthreads();
    float acc[16];
    #pragma unroll
    for (int r = 0; r < 16; r++) acc[r] = 0.f;
    int q = q0 + tid;
    #pragma unroll 8
    for (int i = 0; i < 64; i++) {
        float w = lw2w[(size_t)i * WMC + q];
        #pragma unroll
        for (int r = 0; r < 16; r++) acc[r] += hs[r][i] * w;
    }
    float bv = lw2b[q];
    #pragma unroll
    for (int r = 0; r < 16; r++)
        g_Wm[(size_t)(r0 + r) * WMC + q] = acc[r] + bv;
}

__global__ void meta2b_kernel(const float* __restrict__ lb2w, const float* __restrict__ lb2b) {
    int bt = blockIdx.x, q = threadIdx.x;
    float acc = lb2b[q];
    const float* hrow = g_hid2 + bt * 64;
    #pragma unroll
    for (int i = 0; i < 64; i++) acc += hrow[i] * lb2w[i * G4 + q];
    g_bm[bt * G4 + q] = acc;
}

// Wm[p][g] -> WmT[pg][p] fp16 split, gate-permuted: pg=(hq>>5)*128+(hq&31)*4+gt
__global__ void wmT_kernel() {
    __shared__ float s[32][257];
    int p0 = blockIdx.x * 32, bt = blockIdx.y, tid = threadIdx.x;
    for (int pi = 0; pi < 32; pi++) {
        int p = p0 + pi;
        s[pi][tid] = (p < Pp) ? g_Wm[(size_t)bt * WMC + (size_t)p * G4 + tid] : 0.f;
    }
    __syncthreads();
    int gt = tid >> 6, hq = tid & 63;
    int gp = (hq >> 5) * 128 + (hq & 31) * 4 + gt;
    __half* dh = g_WmTh + (size_t)bt * G4 * KP + (size_t)gp * KP + p0;
    __half* dl = g_WmTl + (size_t)bt * G4 * KP + (size_t)gp * KP + p0;
    #pragma unroll
    for (int c = 0; c < 32; c++) {
        __half hi, lo; splitw(s[c][tid], hi, lo);
        dh[c] = hi; dl[c] = lo;
    }
}

__global__ void decWT_kernel(const float* __restrict__ dW) {
    int g = threadIdx.x;
    int gt = g >> 6, hq = g & 63;
    int gp = (hq >> 5) * 128 + (hq & 31) * 4 + gt;
    for (int p = 0; p < KP; p++) {
        float x = (p < Pp) ? dW[(size_t)p * G4 + g] : 0.f;
        __half hi, lo; splitw(x, hi, lo);
        g_dWh[(size_t)gp * KP + p] = hi;
        g_dWl[(size_t)gp * KP + p] = lo;
    }
}

// ---------------- GEMM1 (GCN): D[q][n] = sum_m combT[q][m] * G_k[n][m] ----------------
__global__ void __launch_bounds__(256, 2) gemm1_kernel() {
    extern __shared__ __half sh[];
    uint32_t sbase = smem_u32(sh);
    const int tid = threadIdx.x, lane = tid & 31, wid = tid >> 5;
    const int wm = wid & 1, wn = wid >> 1;
    const int q0 = blockIdx.x * 128, nb = blockIdx.y * 128, k = blockIdx.z;
    const size_t Gbase = (size_t)k * Nn * Nn;

    float c[4][4][4];
    #pragma unroll
    for (int mt = 0; mt < 4; mt++)
        #pragma unroll
        for (int nt = 0; nt < 4; nt++)
            #pragma unroll
            for (int i = 0; i < 4; i++) c[mt][nt][i] = 0.f;

    auto load_chunk = [&](int ch, int st) {
        int m0 = ch * 32;
        #pragma unroll
        for (int i = 0; i < 2; i++) {
            int idx = tid + 256 * i;
            int r = idx >> 2, c8 = (idx & 3) * 8;
            uint32_t d = sbase + (uint32_t)(st * STAGE + r * PADH + c8) * 2;
            size_t sA = (size_t)(q0 + r) * Nn + m0 + c8;
            cpa16(d, g_cTh + sA);
            cpa16(d + TILEA * 2, g_cTl + sA);
            size_t sB = Gbase + (size_t)(nb + r) * Nn + m0 + c8;
            cpa16(d + 2 * TILEA * 2, g_Gh + sB);
            cpa16(d + 3 * TILEA * 2, g_Gl + sB);
        }
        CP_COMMIT();
    };

    load_chunk(0, 0);
    for (int ch = 0; ch < 32; ch++) {
        if (ch + 1 < 32) { load_chunk(ch + 1, (ch + 1) & 1); CP_WAIT1(); }
        else             { CP_WAIT0(); }
        __syncthreads();
        uint32_t base = sbase + (uint32_t)((ch & 1) * STAGE) * 2;
        frag_mma_block(base, base + TILEA * 2, base + 2 * TILEA * 2, base + 3 * TILEA * 2,
                       lane, wm, wn, c);
        __syncthreads();
    }

    // epilogue: q -> (b, col, p); write split sc halves
    #pragma unroll
    for (int mt = 0; mt < 4; mt++) {
        #pragma unroll
        for (int rh = 0; rh < 2; rh++) {
            int q = q0 + wm * 64 + mt * 16 + (lane >> 2) + rh * 8;
            int b = q / QT, col = q - b * QT;
            if (col >= 65) continue;
            int p = k * 65 + col;
            size_t base = (size_t)(b * Nn) * KP + p;
            #pragma unroll
            for (int nt = 0; nt < 4; nt++) {
                #pragma unroll
                for (int ci = 0; ci < 2; ci++) {
                    int n = nb + wn * 32 + nt * 8 + 2 * (lane & 3) + ci;
                    __half hi, lo; splitw(c[mt][nt][rh * 2 + ci], hi, lo);
                    g_sch[base + (size_t)n * KP] = hi;
                    g_scl[base + (size_t)n * KP] = lo;
                }
            }
        }
    }
}

// ---------------- GEMM2 + LSTM: D[n][pg] over 128 gates (hblk), fused update -------
__global__ void __launch_bounds__(256, 2) gemm2_kernel(int t, int per_batch,
                                                       const float* __restrict__ bext) {
    extern __shared__ __half sh[];
    uint32_t sbase = smem_u32(sh);
    const int tid = threadIdx.x, lane = tid & 31, wid = tid >> 5;
    const int wm = wid & 1, wn = wid >> 1;
    const int n0 = blockIdx.x * 128, b = blockIdx.y, hblk = blockIdx.z;
    const int gblk = hblk * 128;
    const __half *Wth, *Wtl; const float* bb;
    if (per_batch) {
        size_t o = (size_t)(b * Tt + t) * G4 * KP;
        Wth = g_WmTh + o; Wtl = g_WmTl + o; bb = g_bm + (b * Tt + t) * G4;
    } else { Wth = g_dWh; Wtl = g_dWl; bb = bext; }

    float c[4][4][4];
    #pragma unroll
    for (int mt = 0; mt < 4; mt++)
        #pragma unroll
        for (int nt = 0; nt < 4; nt++)
            #pragma unroll
            for (int i = 0; i < 4; i++) c[mt][nt][i] = 0.f;

    auto load_chunk = [&](int ch, int st) {
        int p0 = ch * 32;
        #pragma unroll
        for (int i = 0; i < 2; i++) {
            int idx = tid + 256 * i;
            int r = idx >> 2, c8 = (idx & 3) * 8;
            uint32_t d = sbase + (uint32_t)(st * STAGE + r * PADH + c8) * 2;
            size_t sA = (size_t)(b * Nn + n0 + r) * KP + p0 + c8;
            cpa16(d, g_sch + sA);
            cpa16(d + TILEA * 2, g_scl + sA);
            size_t sB = (size_t)(gblk + r) * KP + p0 + c8;
            cpa16(d + 2 * TILEA * 2, Wth + sB);
            cpa16(d + 3 * TILEA * 2, Wtl + sB);
        }
        CP_COMMIT();
    };

    load_chunk(0, 0);
    for (int ch = 0; ch < 7; ch++) {
        if (ch + 1 < 7) { load_chunk(ch + 1, (ch + 1) & 1); CP_WAIT1(); }
        else            { CP_WAIT0(); }
        __syncthreads();
        uint32_t base = sbase + (uint32_t)((ch & 1) * STAGE) * 2;
        frag_mma_block(base, base + TILEA * 2, base + 2 * TILEA * 2, base + 3 * TILEA * 2,
                       lane, wm, wn, c);
        __syncthreads();
    }

    // stage conv[n_local][pg] in smem (reuses pipeline buffers)
    float* conv = reinterpret_cast<float*>(sh);
    #pragma unroll
    for (int mt = 0; mt < 4; mt++) {
        #pragma unroll
        for (int nt = 0; nt < 4; nt++) {
            #pragma unroll
            for (int i = 0; i < 4; i++) {
                int row = wm * 64 + mt * 16 + (lane >> 2) + (i >> 1) * 8;
                int pg = wn * 32 + nt * 8 + 2 * (lane & 3) + (i & 1);
                conv[row * CPAD2 + pg] = c[mt][nt][i];
            }
        }
    }
    __syncthreads();

    // fused LSTM: hq = hblk*32 + hl; gates at conv[row][hl*4 + {0,1,2,3}]
    #pragma unroll
    for (int u = 0; u < 4; u++) {
        int hl = wid + u * 8;
        int hq = hblk * 32 + hl;
        float bi_ = bb[hq], bf_ = bb[64 + hq], bo_ = bb[128 + hq], bg_ = bb[192 + hq];
        #pragma unroll
        for (int i = 0; i < 4; i++) {
            int row = lane + i * 32;
            int n = n0 + row;
            float4 gv4 = *reinterpret_cast<const float4*>(&conv[row * CPAD2 + hl * 4]);
            float gi = gv4.x + bi_, gf = gv4.y + bf_, go = gv4.z + bo_, gg = gv4.w + bg_;
            float iv = 1.f / (1.f + __expf(-gi));
            float fv = 1.f / (1.f + __expf(-gf));
            float ov = 1.f / (1.f + __expf(-go));
            float gvv = tanhf(gg);
            size_t ci = ((size_t)(b * Hh + hq)) * Nn + n;
            float cv = fv * g_c[ci] + iv * gvv;
            g_c[ci] = cv;
            float hv = ov * tanhf(cv);
            __half hi2, lo2; splitw(hv, hi2, lo2);
            size_t qi = ((size_t)(b * QT + 1 + hq)) * Nn + n;
            g_cTh[qi] = hi2; g_cTl[qi] = lo2;
        }
    }
}

// ---------------- decoder projection ----------------
__global__ void proj_kernel(const float* __restrict__ pw, const float* __restrict__ pb,
                            float* __restrict__ out, int s) {
    int g = blockIdx.x * 256 + threadIdx.x;
    int b = g >> 10, n = g & 1023;
    const __half* hh = g_cTh + ((size_t)(b * QT + 1)) * Nn + n;
    const __half* hl = g_cTl + ((size_t)(b * QT + 1)) * Nn + n;
    float acc = pb[0];
    #pragma unroll
    for (int hq = 0; hq < 64; hq++)
        acc += (__half2float(hh[(size_t)hq * Nn]) + __half2float(hl[(size_t)hq * Nn])) * pw[hq];
    out[((size_t)b * HOR + s) * Nn + n] = acc;
    __half hi, lo; splitw(acc, hi, lo);
    size_t o = ((size_t)(b * QT)) * Nn + n;
    g_cTh[o] = hi; g_cTl[o] = lo;
}

// ---------------- launch ----------------
extern "C" void kernel_launch(void* const* d_in, const int* in_sizes, int n_in,
                              void* d_out, int out_size) {
    const float* G      = (const float*)d_in[0];
    const float* x_seq  = (const float*)d_in[1];
    const float* x_meta = (const float*)d_in[2];
    const float* lw1_w  = (const float*)d_in[3];
    const float* lw1_b  = (const float*)d_in[4];
    const float* lw2_w  = (const float*)d_in[5];
    const float* lw2_b  = (const float*)d_in[6];
    const float* lb1_w  = (const float*)d_in[7];
    const float* lb1_b  = (const float*)d_in[8];
    const float* lb2_w  = (const float*)d_in[9];
    const float* lb2_b  = (const float*)d_in[10];
    const float* dec_W  = (const float*)d_in[11];
    const float* dec_b  = (const float*)d_in[12];
    const float* proj_w = (const float*)d_in[13];
    const float* proj_b = (const float*)d_in[14];
    float* out = (float*)d_out;

    static int attr_done = 0;
    if (!attr_done) {
        cudaFuncSetAttribute(gemm1_kernel, cudaFuncAttributeMaxDynamicSharedMemorySize, SMEMB);
        cudaFuncSetAttribute(gemm2_kernel, cudaFuncAttributeMaxDynamicSharedMemorySize, SMEMB);
        attr_done = 1;
    }

    zero_kernel<<<(Bz * Nn * KP) / 256, 256>>>();
    splitG_kernel<<<(Kk * Nn * Nn) / 256, 256>>>(G);
    meta1_kernel<<<BT, 128>>>(x_meta, lw1_w, lw1_b, lb1_w, lb1_b);
    meta2_kernel<<<dim3(WMC / 256, BT / 16), 256>>>(lw2_w, lw2_b);
    meta2b_kernel<<<BT, 256>>>(lb2_w, lb2_b);
    wmT_kernel<<<dim3(KP / 32, BT), 256>>>();
    decWT_kernel<<<1, 256>>>(dec_W);

    // encoder
    for (int t = 0; t < Tt; t++) {
        xrow_kernel<<<(Bz * Nn) / 256, 256>>>(x_seq, t);
        gemm1_kernel<<<dim3(NQ / 128, Nn / 128, Kk), 256, SMEMB>>>();
        gemm2_kernel<<<dim3(Nn / 128, Bz, 2), 256, SMEMB>>>(t, 1, nullptr);
    }

    // decoder
    zerox_kernel<<<(Bz * Nn) / 256, 256>>>();
    for (int s = 0; s < HOR; s++) {
        gemm1_kernel<<<dim3(NQ / 128, Nn / 128, Kk), 256, SMEMB>>>();
        gemm2_kernel<<<dim3(Nn / 128, Bz, 2), 256, SMEMB>>>(0, 0, dec_b);
        proj_kernel<<<(Bz * Nn) / 256, 256>>>(proj_w, proj_b, out, s);
    }
}